// round 1
// baseline (speedup 1.0000x reference)
#include <cuda_runtime.h>
#include <cuda_bf16.h>
#include <math.h>

// ============================================================================
// ControlledSystem RHS:
//   physics: 2-mass spring/damper + PI-ish controller + Karnopp friction
//   friction magnitudes come from a 1->64->2 MLP(v2) with softplus heads.
//
// Optimization: kinetic_mag(v2) and stiction_limit(v2) are scalar functions of
// the single scalar v2 -> precompute a dense lookup table (post-softplus) in a
// tiny setup kernel, then the main kernel is a pure streaming kernel with one
// 16B table load per element. This removes 64 tanh/elem (MUFU-bound, ~16us)
// and makes the kernel HBM-bound (~44MiB traffic -> ~7us).
// ============================================================================

#define TBL 4096
#define VMIN (-8.0f)
#define INV_STEP 256.0f          // TBL / 16.0  (range [-8, 8])
#define STEP (1.0f / 256.0f)

// scratch (device globals -- no allocation allowed in kernel_launch)
__device__ __align__(16) float4 g_table[TBL];   // (k_i, s_i, k_{i+1}, s_{i+1})
__device__ float g_scalars[4];                  // K, p_ctrl, K*(z_ctrl - p_ctrl)

// ---------------------------------------------------------------------------

__device__ __forceinline__ float softplus_f(float x) {
    // matches jax.nn.softplus = log1p(exp(x)) with overflow guard
    if (x > 15.0f) return x;
    return log1pf(expf(x));
}

__device__ __forceinline__ float2 nn_eval(float v,
                                          const float* __restrict__ W1,
                                          const float* __restrict__ b1,
                                          const float* __restrict__ W2,
                                          const float* __restrict__ b2) {
    float o0 = b2[0];
    float o1 = b2[1];
#pragma unroll 8
    for (int j = 0; j < 64; ++j) {
        float h = tanhf(fmaf(v, W1[j], b1[j]));
        o0 = fmaf(h, W2[2 * j + 0], o0);
        o1 = fmaf(h, W2[2 * j + 1], o1);
    }
    return make_float2(softplus_f(o0), softplus_f(o1));
}

__global__ void setup_kernel(const float* __restrict__ logK,
                             const float* __restrict__ logz,
                             const float* __restrict__ logp,
                             const float* __restrict__ W1,
                             const float* __restrict__ b1,
                             const float* __restrict__ W2,
                             const float* __restrict__ b2) {
    int i = blockIdx.x * blockDim.x + threadIdx.x;
    if (i == 0) {
        float K  = expf(logK[0]);
        float zc = expf(logz[0]);
        float pc = expf(logp[0]);
        g_scalars[0] = K;
        g_scalars[1] = pc;
        g_scalars[2] = K * (zc - pc);
    }
    if (i < TBL) {
        float v0 = VMIN + (float)i * STEP;
        float v1 = VMIN + (float)(i + 1) * STEP;
        float2 a = nn_eval(v0, W1, b1, W2, b2);
        float2 b = nn_eval(v1, W1, b1, W2, b2);
        g_table[i] = make_float4(a.x, a.y, b.x, b.y);
    }
}

// ---------------------------------------------------------------------------
// Per-element physics. Constants: M1=1, M2=1.5, K1=2, K2=3, C1=0.5, C2=0.8,
// KARNOPP_DV=0.01, x2_ref = 0.5*sin(0.5*t).
// ---------------------------------------------------------------------------

__device__ __forceinline__ void rhs_one(float tt, float x1, float v1, float x2,
                                        float v2, float xc,
                                        float K, float pc, float Kzp,
                                        float& d0, float& d1, float& d2,
                                        float& d3, float& d4) {
    float x2r = 0.5f * __sinf(0.5f * tt);
    float e = x2r - x2;
    d4 = fmaf(-pc, xc, e);                 // d_xc
    float u = fmaf(Kzp, xc, K * e);

    float dx = x1 - x2;
    float dv = v1 - v2;
    d0 = v1;                               // dx1
    d1 = u - 2.0f * x1 - 0.5f * v1 - 3.0f * dx - 0.8f * dv;   // dv1 (M1 = 1)
    d2 = v2;                               // dx2

    float F = fmaf(3.0f, dx, 0.8f * dv);   // F_net

    // friction magnitudes via table (post-softplus, linear interp)
    float vcl = fminf(fmaxf(v2, -8.0f), 8.0f);
    float xi = (vcl + 8.0f) * INV_STEP;
    int idx = (int)xi;
    idx = min(idx, TBL - 1);
    float fr = xi - (float)idx;
    float4 ent = __ldg(&g_table[idx]);
    float kin = fmaf(fr, ent.z - ent.x, ent.x);
    float sti = fmaf(fr, ent.w - ent.y, ent.y);

    float Ff = (fabsf(v2) < 0.01f)
                   ? (-fminf(fmaxf(F, -sti), sti))   // static: -clip(F, +/-sti)
                   : (-copysignf(kin, v2));          // kinetic (|v2|>=0.01 => sign=+-1)
    d3 = (F + Ff) * (1.0f / 1.5f);         // dv2 (M2 = 1.5)
}

// ---------------------------------------------------------------------------
// Main streaming kernel, float4 vectorized (requires N % 4 == 0)
// ---------------------------------------------------------------------------

__global__ void rhs_kernel_vec(const float* __restrict__ t,
                               const float* __restrict__ z,
                               float* __restrict__ out, int N) {
    float K   = g_scalars[0];
    float pc  = g_scalars[1];
    float Kzp = g_scalars[2];

    long long i4 = (long long)(blockIdx.x * blockDim.x + threadIdx.x) * 4;
    if (i4 >= N) return;

    long long NN = N;
    float4 t4  = *(const float4*)(t + i4);
    float4 x14 = *(const float4*)(z + i4);
    float4 v14 = *(const float4*)(z + NN + i4);
    float4 x24 = *(const float4*)(z + 2 * NN + i4);
    float4 v24 = *(const float4*)(z + 3 * NN + i4);
    float4 xc4 = *(const float4*)(z + 4 * NN + i4);

    float4 o0, o1, o2, o3, o4;
    rhs_one(t4.x, x14.x, v14.x, x24.x, v24.x, xc4.x, K, pc, Kzp, o0.x, o1.x, o2.x, o3.x, o4.x);
    rhs_one(t4.y, x14.y, v14.y, x24.y, v24.y, xc4.y, K, pc, Kzp, o0.y, o1.y, o2.y, o3.y, o4.y);
    rhs_one(t4.z, x14.z, v14.z, x24.z, v24.z, xc4.z, K, pc, Kzp, o0.z, o1.z, o2.z, o3.z, o4.z);
    rhs_one(t4.w, x14.w, v14.w, x24.w, v24.w, xc4.w, K, pc, Kzp, o0.w, o1.w, o2.w, o3.w, o4.w);

    *(float4*)(out + i4)          = o0;
    *(float4*)(out + NN + i4)     = o1;
    *(float4*)(out + 2 * NN + i4) = o2;
    *(float4*)(out + 3 * NN + i4) = o3;
    *(float4*)(out + 4 * NN + i4) = o4;
}

// scalar fallback (N % 4 != 0)
__global__ void rhs_kernel_scalar(const float* __restrict__ t,
                                  const float* __restrict__ z,
                                  float* __restrict__ out, int N) {
    float K   = g_scalars[0];
    float pc  = g_scalars[1];
    float Kzp = g_scalars[2];

    long long i = blockIdx.x * blockDim.x + threadIdx.x;
    if (i >= N) return;
    long long NN = N;
    float d0, d1, d2, d3, d4;
    rhs_one(t[i], z[i], z[NN + i], z[2 * NN + i], z[3 * NN + i], z[4 * NN + i],
            K, pc, Kzp, d0, d1, d2, d3, d4);
    out[i]          = d0;
    out[NN + i]     = d1;
    out[2 * NN + i] = d2;
    out[3 * NN + i] = d3;
    out[4 * NN + i] = d4;
}

// ---------------------------------------------------------------------------

extern "C" void kernel_launch(void* const* d_in, const int* in_sizes, int n_in,
                              void* d_out, int out_size) {
    const float* t    = (const float*)d_in[0];
    const float* z    = (const float*)d_in[1];
    const float* logK = (const float*)d_in[2];
    const float* logz = (const float*)d_in[3];
    const float* logp = (const float*)d_in[4];
    const float* W1   = (const float*)d_in[5];
    const float* b1   = (const float*)d_in[6];
    const float* W2   = (const float*)d_in[7];
    const float* b2   = (const float*)d_in[8];
    float* out = (float*)d_out;
    int N = in_sizes[0];

    setup_kernel<<<(TBL + 255) / 256, 256>>>(logK, logz, logp, W1, b1, W2, b2);

    if ((N & 3) == 0) {
        int nthreads = N / 4;
        rhs_kernel_vec<<<(nthreads + 255) / 256, 256>>>(t, z, out, N);
    } else {
        rhs_kernel_scalar<<<(N + 255) / 256, 256>>>(t, z, out, N);
    }
}

// round 2
// speedup vs baseline: 1.2243x; 1.2243x over previous
#include <cuda_runtime.h>
#include <cuda_bf16.h>
#include <math.h>

// ============================================================================
// ControlledSystem RHS (2-mass + controller + Karnopp friction w/ MLP mags).
//
// R1 findings: setup kernel was ~9us (only 16 blocks -> 16 SMs doing serial
// tanh chains); main kernel latency-bound (issue 19%, DRAM 27%).
// R2 changes:
//   - setup: one WARP per table node (lane = 2 hidden units, shuffle reduce)
//     -> full-chip parallel, ~1.3us.
//   - main: 8 elems/thread, all loads front-batched (MLP_p1 ~ 20) to hide
//     the LDG(v2) -> table-LDG dependent latency chain; streaming ld/st
//     hints keep the 64KB table hot in L1/L2.
// ============================================================================

#define TBL 4096
#define NNODES (TBL + 1)
#define VMIN (-8.0f)
#define INV_STEP 256.0f          // TBL / 16.0  (range [-8, 8])
#define STEP (1.0f / 256.0f)

__device__ __align__(16) float4 g_table[TBL];   // (k_i, s_i, k_{i+1}, s_{i+1})
__device__ __align__(8)  float2 g_nodes[NNODES];
__device__ float g_scalars[4];                  // K, p_ctrl, K*(z_ctrl - p_ctrl)

// ---------------------------------------------------------------------------

__device__ __forceinline__ float softplus_f(float x) {
    if (x > 15.0f) return x;
    return log1pf(expf(x));
}

// One warp per node; lane handles hidden units (lane) and (lane+32).
__global__ void setup_nodes(const float* __restrict__ logK,
                            const float* __restrict__ logz,
                            const float* __restrict__ logp,
                            const float* __restrict__ W1,
                            const float* __restrict__ b1,
                            const float* __restrict__ W2,
                            const float* __restrict__ b2) {
    int gtid = blockIdx.x * blockDim.x + threadIdx.x;
    int node = gtid >> 5;
    int lane = gtid & 31;

    if (gtid == 0) {
        float K  = expf(logK[0]);
        float zc = expf(logz[0]);
        float pc = expf(logp[0]);
        g_scalars[0] = K;
        g_scalars[1] = pc;
        g_scalars[2] = K * (zc - pc);
    }
    if (node >= NNODES) return;

    float v = VMIN + (float)node * STEP;
    float o0 = 0.0f, o1 = 0.0f;
#pragma unroll
    for (int r = 0; r < 2; ++r) {
        int j = lane + 32 * r;
        float h = tanhf(fmaf(v, W1[j], b1[j]));
        o0 = fmaf(h, W2[2 * j + 0], o0);
        o1 = fmaf(h, W2[2 * j + 1], o1);
    }
#pragma unroll
    for (int off = 16; off > 0; off >>= 1) {
        o0 += __shfl_down_sync(0xffffffffu, o0, off);
        o1 += __shfl_down_sync(0xffffffffu, o1, off);
    }
    if (lane == 0) {
        o0 += b2[0];
        o1 += b2[1];
        g_nodes[node] = make_float2(softplus_f(o0), softplus_f(o1));
    }
}

// Pack adjacent nodes into float4 so the main kernel does ONE 16B table load.
__global__ void pack_table() {
    int i = blockIdx.x * blockDim.x + threadIdx.x;
    if (i < TBL) {
        float2 a = g_nodes[i];
        float2 b = g_nodes[i + 1];
        g_table[i] = make_float4(a.x, a.y, b.x, b.y);
    }
}

// ---------------------------------------------------------------------------
// Per-element physics. M1=1, M2=1.5, K1=2, K2=3, C1=0.5, C2=0.8, dv=0.01,
// x2_ref = 0.5*sin(0.5*t).
// ---------------------------------------------------------------------------

__device__ __forceinline__ void rhs_one(float tt, float x1, float v1, float x2,
                                        float v2, float xc, float4 ent, float fr,
                                        float K, float pc, float Kzp,
                                        float& d0, float& d1, float& d2,
                                        float& d3, float& d4) {
    float x2r = 0.5f * __sinf(0.5f * tt);
    float e = x2r - x2;
    d4 = fmaf(-pc, xc, e);                 // d_xc
    float u = fmaf(Kzp, xc, K * e);

    float dx = x1 - x2;
    float dv = v1 - v2;
    d0 = v1;                               // dx1
    d1 = u - 2.0f * x1 - 0.5f * v1 - 3.0f * dx - 0.8f * dv;   // dv1 (M1=1)
    d2 = v2;                               // dx2

    float F = fmaf(3.0f, dx, 0.8f * dv);   // F_net

    float kin = fmaf(fr, ent.z - ent.x, ent.x);
    float sti = fmaf(fr, ent.w - ent.y, ent.y);

    float Ff = (fabsf(v2) < 0.01f)
                   ? (-fminf(fmaxf(F, -sti), sti))   // static: -clip(F,+/-sti)
                   : (-copysignf(kin, v2));          // kinetic
    d3 = (F + Ff) * (1.0f / 1.5f);         // dv2 (M2=1.5)
}

__device__ __forceinline__ void table_idx(float v2, int& idx, float& fr) {
    float vcl = fminf(fmaxf(v2, -8.0f), 8.0f);
    float xi = (vcl + 8.0f) * INV_STEP;
    int i = (int)xi;
    i = min(i, TBL - 1);
    fr = xi - (float)i;
    idx = i;
}

// ---------------------------------------------------------------------------
// Main streaming kernel: 8 elements per thread (two float4 groups), all
// input loads + table loads issued before compute (front-batched MLP).
// ---------------------------------------------------------------------------

__global__ __launch_bounds__(256) void rhs_kernel_vec8(
    const float* __restrict__ t,
    const float* __restrict__ z,
    float* __restrict__ out, int N) {
    float K   = g_scalars[0];
    float pc  = g_scalars[1];
    float Kzp = g_scalars[2];

    long long base = (long long)(blockIdx.x * blockDim.x + threadIdx.x) * 8;
    if (base >= N) return;
    long long NN = N;

    const float4* tA  = (const float4*)(t + base);
    const float4* zA  = (const float4*)(z + base);
    const float4* v1A = (const float4*)(z + NN + base);
    const float4* x2A = (const float4*)(z + 2 * NN + base);
    const float4* v2A = (const float4*)(z + 3 * NN + base);
    const float4* xcA = (const float4*)(z + 4 * NN + base);

    // front-batch all 12 input LDG.128 (streaming: one-shot data)
    float4 v2a = __ldcs(v2A);     float4 v2b = __ldcs(v2A + 1);
    float4 ta  = __ldcs(tA);      float4 tb  = __ldcs(tA + 1);
    float4 x1a = __ldcs(zA);      float4 x1b = __ldcs(zA + 1);
    float4 v1a = __ldcs(v1A);     float4 v1b = __ldcs(v1A + 1);
    float4 x2a = __ldcs(x2A);     float4 x2b = __ldcs(x2A + 1);
    float4 xca = __ldcs(xcA);     float4 xcb = __ldcs(xcA + 1);

    // table lookups as soon as v2 is available
    int   i0, i1, i2, i3, i4, i5, i6, i7;
    float f0, f1, f2, f3, f4, f5, f6, f7;
    table_idx(v2a.x, i0, f0); table_idx(v2a.y, i1, f1);
    table_idx(v2a.z, i2, f2); table_idx(v2a.w, i3, f3);
    table_idx(v2b.x, i4, f4); table_idx(v2b.y, i5, f5);
    table_idx(v2b.z, i6, f6); table_idx(v2b.w, i7, f7);
    float4 e0 = __ldg(&g_table[i0]);
    float4 e1 = __ldg(&g_table[i1]);
    float4 e2 = __ldg(&g_table[i2]);
    float4 e3 = __ldg(&g_table[i3]);
    float4 e4 = __ldg(&g_table[i4]);
    float4 e5 = __ldg(&g_table[i5]);
    float4 e6 = __ldg(&g_table[i6]);
    float4 e7 = __ldg(&g_table[i7]);

    float4 o0a, o1a, o2a, o3a, o4a;
    float4 o0b, o1b, o2b, o3b, o4b;
    rhs_one(ta.x, x1a.x, v1a.x, x2a.x, v2a.x, xca.x, e0, f0, K, pc, Kzp, o0a.x, o1a.x, o2a.x, o3a.x, o4a.x);
    rhs_one(ta.y, x1a.y, v1a.y, x2a.y, v2a.y, xca.y, e1, f1, K, pc, Kzp, o0a.y, o1a.y, o2a.y, o3a.y, o4a.y);
    rhs_one(ta.z, x1a.z, v1a.z, x2a.z, v2a.z, xca.z, e2, f2, K, pc, Kzp, o0a.z, o1a.z, o2a.z, o3a.z, o4a.z);
    rhs_one(ta.w, x1a.w, v1a.w, x2a.w, v2a.w, xca.w, e3, f3, K, pc, Kzp, o0a.w, o1a.w, o2a.w, o3a.w, o4a.w);
    rhs_one(tb.x, x1b.x, v1b.x, x2b.x, v2b.x, xcb.x, e4, f4, K, pc, Kzp, o0b.x, o1b.x, o2b.x, o3b.x, o4b.x);
    rhs_one(tb.y, x1b.y, v1b.y, x2b.y, v2b.y, xcb.y, e5, f5, K, pc, Kzp, o0b.y, o1b.y, o2b.y, o3b.y, o4b.y);
    rhs_one(tb.z, x1b.z, v1b.z, x2b.z, v2b.z, xcb.z, e6, f6, K, pc, Kzp, o0b.z, o1b.z, o2b.z, o3b.z, o4b.z);
    rhs_one(tb.w, x1b.w, v1b.w, x2b.w, v2b.w, xcb.w, e7, f7, K, pc, Kzp, o0b.w, o1b.w, o2b.w, o3b.w, o4b.w);

    float4* O0 = (float4*)(out + base);
    float4* O1 = (float4*)(out + NN + base);
    float4* O2 = (float4*)(out + 2 * NN + base);
    float4* O3 = (float4*)(out + 3 * NN + base);
    float4* O4 = (float4*)(out + 4 * NN + base);
    __stcs(O0, o0a); __stcs(O0 + 1, o0b);
    __stcs(O1, o1a); __stcs(O1 + 1, o1b);
    __stcs(O2, o2a); __stcs(O2 + 1, o2b);
    __stcs(O3, o3a); __stcs(O3 + 1, o3b);
    __stcs(O4, o4a); __stcs(O4 + 1, o4b);
}

// scalar fallback (N % 8 != 0)
__global__ void rhs_kernel_scalar(const float* __restrict__ t,
                                  const float* __restrict__ z,
                                  float* __restrict__ out, int N) {
    float K   = g_scalars[0];
    float pc  = g_scalars[1];
    float Kzp = g_scalars[2];

    long long i = blockIdx.x * blockDim.x + threadIdx.x;
    if (i >= N) return;
    long long NN = N;
    float v2 = z[3 * NN + i];
    int idx; float fr;
    table_idx(v2, idx, fr);
    float4 ent = __ldg(&g_table[idx]);
    float d0, d1, d2, d3, d4;
    rhs_one(t[i], z[i], z[NN + i], z[2 * NN + i], v2, z[4 * NN + i],
            ent, fr, K, pc, Kzp, d0, d1, d2, d3, d4);
    out[i]          = d0;
    out[NN + i]     = d1;
    out[2 * NN + i] = d2;
    out[3 * NN + i] = d3;
    out[4 * NN + i] = d4;
}

// ---------------------------------------------------------------------------

extern "C" void kernel_launch(void* const* d_in, const int* in_sizes, int n_in,
                              void* d_out, int out_size) {
    const float* t    = (const float*)d_in[0];
    const float* z    = (const float*)d_in[1];
    const float* logK = (const float*)d_in[2];
    const float* logz = (const float*)d_in[3];
    const float* logp = (const float*)d_in[4];
    const float* W1   = (const float*)d_in[5];
    const float* b1   = (const float*)d_in[6];
    const float* W2   = (const float*)d_in[7];
    const float* b2   = (const float*)d_in[8];
    float* out = (float*)d_out;
    int N = in_sizes[0];

    // one warp per node: NNODES*32 threads
    int setup_threads = NNODES * 32;
    setup_nodes<<<(setup_threads + 255) / 256, 256>>>(logK, logz, logp, W1, b1, W2, b2);
    pack_table<<<(TBL + 255) / 256, 256>>>();

    if ((N & 7) == 0) {
        int nthreads = N / 8;
        rhs_kernel_vec8<<<(nthreads + 255) / 256, 256>>>(t, z, out, N);
    } else {
        rhs_kernel_scalar<<<(N + 255) / 256, 256>>>(t, z, out, N);
    }
}

// round 4
// speedup vs baseline: 1.2743x; 1.0409x over previous
#include <cuda_runtime.h>
#include <cuda_bf16.h>
#include <math.h>

// ============================================================================
// ControlledSystem RHS (2-mass + controller + Karnopp friction w/ MLP mags).
//
// R2 post-mortem: main kernel was L1tex-wavefront-bound on the scattered
// 64KB table gather (~26 line-replays per LDG.128 gather); setup was 5.4us
// of redundant libm tanh over 4097 warps.
// R3:
//   - table shrunk to 512 intervals (lerp err ~1e-5 << 1e-3 threshold),
//     setup = 513 warps with __expf-based tanh/softplus  (~0.9us)
//   - main kernel stages the 4.1KB node table in SHARED MEMORY; gather is
//     two LDS.64 per element instead of a scattered global LDG.128
//   - streaming __ldcs/__stcs for the one-shot input/output vectors
// ============================================================================

#define TBL 512
#define NNODES (TBL + 1)
#define VMIN (-8.0f)
#define INV_STEP 32.0f           // TBL / 16.0  (range [-8, 8])
#define STEP (1.0f / 32.0f)

__device__ __align__(8) float2 g_nodes[NNODES];  // (kinetic, stiction) post-softplus
__device__ float g_scalars[4];                   // K, p_ctrl, K*(z_ctrl - p_ctrl)

// ---------------------------------------------------------------------------

__device__ __forceinline__ float fast_tanh(float x) {
    // tanh(x) = 1 - 2/(exp(2x)+1); __expf(inf)->inf handled naturally
    return 1.0f - 2.0f / (__expf(2.0f * x) + 1.0f);
}

__device__ __forceinline__ float fast_softplus(float x) {
    if (x > 15.0f) return x;
    return log1pf(__expf(x));
}

// One warp per node; lane handles hidden units (lane) and (lane+32).
__global__ void setup_nodes(const float* __restrict__ logK,
                            const float* __restrict__ logz,
                            const float* __restrict__ logp,
                            const float* __restrict__ W1,
                            const float* __restrict__ b1,
                            const float* __restrict__ W2,
                            const float* __restrict__ b2) {
    int gtid = blockIdx.x * blockDim.x + threadIdx.x;
    int node = gtid >> 5;
    int lane = gtid & 31;

    if (gtid == 0) {
        float K  = expf(logK[0]);
        float zc = expf(logz[0]);
        float pc = expf(logp[0]);
        g_scalars[0] = K;
        g_scalars[1] = pc;
        g_scalars[2] = K * (zc - pc);
    }
    if (node >= NNODES) return;

    float v = VMIN + (float)node * STEP;
    float o0 = 0.0f, o1 = 0.0f;
#pragma unroll
    for (int r = 0; r < 2; ++r) {
        int j = lane + 32 * r;
        float h = fast_tanh(fmaf(v, W1[j], b1[j]));
        o0 = fmaf(h, W2[2 * j + 0], o0);
        o1 = fmaf(h, W2[2 * j + 1], o1);
    }
#pragma unroll
    for (int off = 16; off > 0; off >>= 1) {
        o0 += __shfl_down_sync(0xffffffffu, o0, off);
        o1 += __shfl_down_sync(0xffffffffu, o1, off);
    }
    if (lane == 0) {
        o0 += b2[0];
        o1 += b2[1];
        g_nodes[node] = make_float2(fast_softplus(o0), fast_softplus(o1));
    }
}

// ---------------------------------------------------------------------------
// Per-element physics. M1=1, M2=1.5, K1=2, K2=3, C1=0.5, C2=0.8, dv=0.01,
// x2_ref = 0.5*sin(0.5*t).
// ---------------------------------------------------------------------------

__device__ __forceinline__ void rhs_one(float tt, float x1, float v1, float x2,
                                        float v2, float xc,
                                        float kin, float sti,
                                        float K, float pc, float Kzp,
                                        float& d0, float& d1, float& d2,
                                        float& d3, float& d4) {
    float x2r = 0.5f * __sinf(0.5f * tt);
    float e = x2r - x2;
    d4 = fmaf(-pc, xc, e);                 // d_xc
    float u = fmaf(Kzp, xc, K * e);

    float dx = x1 - x2;
    float dv = v1 - v2;
    d0 = v1;                               // dx1
    d1 = u - 2.0f * x1 - 0.5f * v1 - 3.0f * dx - 0.8f * dv;   // dv1 (M1=1)
    d2 = v2;                               // dx2

    float F = fmaf(3.0f, dx, 0.8f * dv);   // F_net

    float Ff = (fabsf(v2) < 0.01f)
                   ? (-fminf(fmaxf(F, -sti), sti))   // static: -clip(F,+/-sti)
                   : (-copysignf(kin, v2));          // kinetic
    d3 = (F + Ff) * (1.0f / 1.5f);         // dv2 (M2=1.5)
}

// table lookup from shared memory, linear interpolation
__device__ __forceinline__ void lookup(const float2* __restrict__ s_nodes,
                                       float v2, float& kin, float& sti) {
    float vcl = fminf(fmaxf(v2, -8.0f), 8.0f);
    float xi = (vcl + 8.0f) * INV_STEP;
    int idx = (int)xi;
    idx = min(idx, TBL - 1);
    float fr = xi - (float)idx;
    float2 a = s_nodes[idx];
    float2 b = s_nodes[idx + 1];
    kin = fmaf(fr, b.x - a.x, a.x);
    sti = fmaf(fr, b.y - a.y, a.y);
}

// ---------------------------------------------------------------------------
// Main streaming kernel: 8 elements per thread (two float4 groups), table in
// shared memory, all global loads front-batched.
// ---------------------------------------------------------------------------

__global__ __launch_bounds__(256) void rhs_kernel_vec8(
    const float* __restrict__ t,
    const float* __restrict__ z,
    float* __restrict__ out, int N) {
    __shared__ __align__(8) float2 s_nodes[NNODES];
    for (int i = threadIdx.x; i < NNODES; i += blockDim.x) {
        s_nodes[i] = g_nodes[i];
    }

    float K   = g_scalars[0];
    float pc  = g_scalars[1];
    float Kzp = g_scalars[2];

    long long base = (long long)(blockIdx.x * blockDim.x + threadIdx.x) * 8;
    long long NN = N;

    // front-batch all 12 input LDG.128 while the smem fill is in flight
    const float4* tA  = (const float4*)(t + base);
    const float4* zA  = (const float4*)(z + base);
    const float4* v1A = (const float4*)(z + NN + base);
    const float4* x2A = (const float4*)(z + 2 * NN + base);
    const float4* v2A = (const float4*)(z + 3 * NN + base);
    const float4* xcA = (const float4*)(z + 4 * NN + base);

    float4 v2a = __ldcs(v2A);     float4 v2b = __ldcs(v2A + 1);
    float4 ta  = __ldcs(tA);      float4 tb  = __ldcs(tA + 1);
    float4 x1a = __ldcs(zA);      float4 x1b = __ldcs(zA + 1);
    float4 v1a = __ldcs(v1A);     float4 v1b = __ldcs(v1A + 1);
    float4 x2a = __ldcs(x2A);     float4 x2b = __ldcs(x2A + 1);
    float4 xca = __ldcs(xcA);     float4 xcb = __ldcs(xcA + 1);

    __syncthreads();   // smem table ready

    float k0, s0, k1, s1, k2, s2, k3, s3, k4, s4, k5, s5, k6, s6, k7, s7;
    lookup(s_nodes, v2a.x, k0, s0); lookup(s_nodes, v2a.y, k1, s1);
    lookup(s_nodes, v2a.z, k2, s2); lookup(s_nodes, v2a.w, k3, s3);
    lookup(s_nodes, v2b.x, k4, s4); lookup(s_nodes, v2b.y, k5, s5);
    lookup(s_nodes, v2b.z, k6, s6); lookup(s_nodes, v2b.w, k7, s7);

    float4 o0a, o1a, o2a, o3a, o4a;
    float4 o0b, o1b, o2b, o3b, o4b;
    rhs_one(ta.x, x1a.x, v1a.x, x2a.x, v2a.x, xca.x, k0, s0, K, pc, Kzp, o0a.x, o1a.x, o2a.x, o3a.x, o4a.x);
    rhs_one(ta.y, x1a.y, v1a.y, x2a.y, v2a.y, xca.y, k1, s1, K, pc, Kzp, o0a.y, o1a.y, o2a.y, o3a.y, o4a.y);
    rhs_one(ta.z, x1a.z, v1a.z, x2a.z, v2a.z, xca.z, k2, s2, K, pc, Kzp, o0a.z, o1a.z, o2a.z, o3a.z, o4a.z);
    rhs_one(ta.w, x1a.w, v1a.w, x2a.w, v2a.w, xca.w, k3, s3, K, pc, Kzp, o0a.w, o1a.w, o2a.w, o3a.w, o4a.w);
    rhs_one(tb.x, x1b.x, v1b.x, x2b.x, v2b.x, xcb.x, k4, s4, K, pc, Kzp, o0b.x, o1b.x, o2b.x, o3b.x, o4b.x);
    rhs_one(tb.y, x1b.y, v1b.y, x2b.y, v2b.y, xcb.y, k5, s5, K, pc, Kzp, o0b.y, o1b.y, o2b.y, o3b.y, o4b.y);
    rhs_one(tb.z, x1b.z, v1b.z, x2b.z, v2b.z, xcb.z, k6, s6, K, pc, Kzp, o0b.z, o1b.z, o2b.z, o3b.z, o4b.z);
    rhs_one(tb.w, x1b.w, v1b.w, x2b.w, v2b.w, xcb.w, k7, s7, K, pc, Kzp, o0b.w, o1b.w, o2b.w, o3b.w, o4b.w);

    float4* O0 = (float4*)(out + base);
    float4* O1 = (float4*)(out + NN + base);
    float4* O2 = (float4*)(out + 2 * NN + base);
    float4* O3 = (float4*)(out + 3 * NN + base);
    float4* O4 = (float4*)(out + 4 * NN + base);
    __stcs(O0, o0a); __stcs(O0 + 1, o0b);
    __stcs(O1, o1a); __stcs(O1 + 1, o1b);
    __stcs(O2, o2a); __stcs(O2 + 1, o2b);
    __stcs(O3, o3a); __stcs(O3 + 1, o3b);
    __stcs(O4, o4a); __stcs(O4 + 1, o4b);
}

// scalar fallback (N % 8 != 0) -- table straight from global
__global__ void rhs_kernel_scalar(const float* __restrict__ t,
                                  const float* __restrict__ z,
                                  float* __restrict__ out, int N) {
    float K   = g_scalars[0];
    float pc  = g_scalars[1];
    float Kzp = g_scalars[2];

    long long i = blockIdx.x * blockDim.x + threadIdx.x;
    if (i >= N) return;
    long long NN = N;
    float v2 = z[3 * NN + i];

    float vcl = fminf(fmaxf(v2, -8.0f), 8.0f);
    float xi = (vcl + 8.0f) * INV_STEP;
    int idx = (int)xi;
    idx = min(idx, TBL - 1);
    float fr = xi - (float)idx;
    float2 a = g_nodes[idx];
    float2 b = g_nodes[idx + 1];
    float kin = fmaf(fr, b.x - a.x, a.x);
    float sti = fmaf(fr, b.y - a.y, a.y);

    float d0, d1, d2, d3, d4;
    rhs_one(t[i], z[i], z[NN + i], z[2 * NN + i], v2, z[4 * NN + i],
            kin, sti, K, pc, Kzp, d0, d1, d2, d3, d4);
    out[i]          = d0;
    out[NN + i]     = d1;
    out[2 * NN + i] = d2;
    out[3 * NN + i] = d3;
    out[4 * NN + i] = d4;
}

// ---------------------------------------------------------------------------

extern "C" void kernel_launch(void* const* d_in, const int* in_sizes, int n_in,
                              void* d_out, int out_size) {
    const float* t    = (const float*)d_in[0];
    const float* z    = (const float*)d_in[1];
    const float* logK = (const float*)d_in[2];
    const float* logz = (const float*)d_in[3];
    const float* logp = (const float*)d_in[4];
    const float* W1   = (const float*)d_in[5];
    const float* b1   = (const float*)d_in[6];
    const float* W2   = (const float*)d_in[7];
    const float* b2   = (const float*)d_in[8];
    float* out = (float*)d_out;
    int N = in_sizes[0];

    // one warp per node
    int setup_threads = NNODES * 32;
    setup_nodes<<<(setup_threads + 255) / 256, 256>>>(logK, logz, logp, W1, b1, W2, b2);

    if ((N & 7) == 0) {
        int nthreads = N / 8;
        rhs_kernel_vec8<<<(nthreads + 255) / 256, 256>>>(t, z, out, N);
    } else {
        rhs_kernel_scalar<<<(N + 255) / 256, 256>>>(t, z, out, N);
    }
}